// round 12
// baseline (speedup 1.0000x reference)
#include <cuda_runtime.h>
#include <cuda_fp16.h>
#include <cstdint>

// ConvEmbedding: out[n,i] = normalize_row( sum_k w[i,k]*x[n,i+k] + b[i] )
// C = X(16384x2048) @ W_band(512x2048)^T, fp16 inputs, fp32 accumulation.
// R12: fused A fp32->fp16 convert inside GEMM at occupancy 1 (255-reg budget;
//      R10's spill failure removed). B: cp.async 3-stage. prep = band only.

#define N_ROWS 16384
#define D_DIM  2048
#define E_DIM  512
#define K_DIM  1537

#define BM 128
#define BN 128
#define BK 64
#define PITCH 72                 // fp16 elems per smem row (144 B)
#define NITER 26                 // 1664 / 64, uniform for every E tile
#define THREADS 256

#define TILE_SMEM (BM * PITCH * 2)           // 18432 B per tile
// smem layout: B stages 0..2, A buffers 3..4
#define SMEM_BYTES (5 * TILE_SMEM)           // 92160 B

// ---------------- scratch (device globals) ----------------------------------
__device__ __half g_Wh[(size_t)E_DIM * D_DIM];

// ---------------- kernel 1: build banded W (fp16) ----------------------------
__global__ void build_band_kernel(const float* __restrict__ w) {
    const int i = blockIdx.x;  // 0..511
    const float* wrow = w + (size_t)i * K_DIM;
    for (int c = threadIdx.x; c < D_DIM; c += blockDim.x) {
        const int k = c - i;
        const float val = (k >= 0 && k < K_DIM) ? wrow[k] : 0.0f;
        g_Wh[(size_t)i * D_DIM + c] = __float2half_rn(val);
    }
}

// ---------------- helpers -----------------------------------------------------
__device__ __forceinline__ void ldm_x4(uint32_t* r, uint32_t saddr) {
    asm volatile("ldmatrix.sync.aligned.m8n8.x4.shared.b16 {%0,%1,%2,%3}, [%4];"
                 : "=r"(r[0]), "=r"(r[1]), "=r"(r[2]), "=r"(r[3]) : "r"(saddr));
}
__device__ __forceinline__ void mma_f16(float* d, const uint32_t* a, const uint32_t* b) {
    asm volatile(
        "mma.sync.aligned.m16n8k16.row.col.f32.f16.f16.f32 "
        "{%0,%1,%2,%3}, {%4,%5,%6,%7}, {%8,%9}, {%0,%1,%2,%3};"
        : "+f"(d[0]), "+f"(d[1]), "+f"(d[2]), "+f"(d[3])
        : "r"(a[0]), "r"(a[1]), "r"(a[2]), "r"(a[3]), "r"(b[0]), "r"(b[1]));
}
__device__ __forceinline__ void cp_async16(uint32_t saddr, const void* gaddr) {
    asm volatile("cp.async.cg.shared.global [%0], [%1], 16;" :: "r"(saddr), "l"(gaddr));
}
// 16 fp32 -> 8 packed fp16x2
__device__ __forceinline__ void cvt16h(const float* v, uint32_t* h) {
    #pragma unroll
    for (int j = 0; j < 8; j++) {
        const __half2 p = __float22half2_rn(make_float2(v[j * 2], v[j * 2 + 1]));
        h[j] = *reinterpret_cast<const uint32_t*>(&p);
    }
}

// ---------------- kernel 2: fp16 GEMM, fused A-convert, occ 1 -----------------
// Warp layout: 2 warps along M (tile 64) x 4 warps along N (tile 32).
__global__ __launch_bounds__(THREADS, 1)
void mma_gemm_kernel(const float* __restrict__ X, float* __restrict__ C) {
    extern __shared__ __align__(128) char smem[];
    const uint32_t sb = (uint32_t)__cvta_generic_to_shared(smem);

    const int tid  = threadIdx.x;
    const int lane = tid & 31;
    const int wid  = tid >> 5;
    const int wm   = wid & 1;
    const int wn   = wid >> 1;
    const int bx = blockIdx.x;         // E tile (0..3)
    const int by = blockIdx.y;         // batch tile (0..127)
    const int i0 = bx * BN;
    const int kStart = i0;

    // ---- A duty: thread owns row tid>>1, 32 fp16 cols at (tid&1)*32
    const int arow  = tid >> 1;
    const int ahalf = (tid & 1) * 32;
    const float* Ap = X + (size_t)(by * BM + arow) * D_DIM + ahalf;
    const uint32_t aStsB = (uint32_t)(arow * PITCH + ahalf) * 2;  // byte off in tile

    // ---- B loader (cp.async): tile = 128 rows x 64 fp16; 1024 x16B chunks
    const __half* Bsrc = g_Wh + (size_t)i0 * D_DIM;
    int brow[4], bchk[4];
    #pragma unroll
    for (int i = 0; i < 4; i++) {
        const int v = tid + i * THREADS;   // 0..1023
        brow[i] = v >> 3;
        bchk[i] = v & 7;
    }

    const uint32_t aoff = ((uint32_t)((wm * 64 + (lane & 15)) * PITCH + (lane >> 4) * 8)) * 2;
    const uint32_t boff = ((uint32_t)((wn * 32 + (lane >> 4) * 8 + (lane & 7)) * PITCH
                                      + ((lane >> 3) & 1) * 8)) * 2;

    float acc[4][4][4];
    #pragma unroll
    for (int mt = 0; mt < 4; mt++)
        #pragma unroll
        for (int nt = 0; nt < 4; nt++)
            #pragma unroll
            for (int q = 0; q < 4; q++) acc[mt][nt][q] = 0.0f;

    auto load_B = [&](int s, int k0) {
        const uint32_t stg = sb + (uint32_t)s * TILE_SMEM;
        #pragma unroll
        for (int i = 0; i < 4; i++)
            cp_async16(stg + (uint32_t)(brow[i] * PITCH * 2 + bchk[i] * 16),
                       Bsrc + (size_t)brow[i] * D_DIM + k0 + bchk[i] * 8);
        asm volatile("cp.async.commit_group;" ::: "memory");
    };

    // ---- prologue: B(0), B(1) in flight; A(0) converted and stored
    load_B(0, kStart);
    load_B(1, kStart + BK);
    {
        float av[32]; uint32_t h[8];
        char* A0 = smem + 3 * TILE_SMEM;
        #pragma unroll
        for (int q = 0; q < 8; q++)
            *reinterpret_cast<float4*>(&av[q * 4]) =
                *reinterpret_cast<const float4*>(Ap + kStart + q * 4);
        cvt16h(&av[0], h);
        *reinterpret_cast<uint4*>(A0 + aStsB)      = *reinterpret_cast<uint4*>(&h[0]);
        *reinterpret_cast<uint4*>(A0 + aStsB + 16) = *reinterpret_cast<uint4*>(&h[4]);
        cvt16h(&av[16], h);
        *reinterpret_cast<uint4*>(A0 + aStsB + 32) = *reinterpret_cast<uint4*>(&h[0]);
        *reinterpret_cast<uint4*>(A0 + aStsB + 48) = *reinterpret_cast<uint4*>(&h[4]);
    }
    asm volatile("cp.async.wait_group 1;" ::: "memory");
    __syncthreads();

    for (int it = 0; it < NITER; it++) {
        const int prep = (it + 1 < NITER);
        if (it + 2 < NITER)
            load_B((it + 2) % 3, kStart + (it + 2) * BK);

        const uint32_t sA = sb + (uint32_t)(3 + (it & 1)) * TILE_SMEM + aoff;
        const uint32_t sB = sb + (uint32_t)(it % 3) * TILE_SMEM + boff;
        char* An = smem + (3 + ((it + 1) & 1)) * TILE_SMEM;   // A buffer for it+1
        const int kn = kStart + (it + 1) * BK;

        float av[32];
        if (prep) {
            #pragma unroll
            for (int q = 0; q < 8; q++)
                *reinterpret_cast<float4*>(&av[q * 4]) =
                    *reinterpret_cast<const float4*>(Ap + kn + q * 4);
        }

        #pragma unroll
        for (int k16 = 0; k16 < 4; k16++) {
            const uint32_t ko = k16 * 32;  // 16 fp16 = 32 B
            uint32_t bfr[8];
            #pragma unroll
            for (int bt = 0; bt < 2; bt++)
                ldm_x4(&bfr[bt * 4], sB + (uint32_t)(bt * 16 * PITCH) * 2 + ko);
            #pragma unroll
            for (int mp = 0; mp < 2; mp++) {
                uint32_t a[8];
                #pragma unroll
                for (int m2 = 0; m2 < 2; m2++)
                    ldm_x4(&a[m2 * 4], sA + (uint32_t)((mp * 2 + m2) * 16 * PITCH) * 2 + ko);
                #pragma unroll
                for (int m2 = 0; m2 < 2; m2++)
                    #pragma unroll
                    for (int nt = 0; nt < 4; nt++)
                        mma_f16(acc[mp * 2 + m2][nt], &a[m2 * 4], &bfr[nt * 2]);
            }

            // single convert burst mid-body: STS completes before next iter's
            // ldmatrix on An (guarded by trailing __syncthreads)
            if (k16 == 2 && prep) {
                uint32_t h[8];
                cvt16h(&av[0], h);
                *reinterpret_cast<uint4*>(An + aStsB)      = *reinterpret_cast<uint4*>(&h[0]);
                *reinterpret_cast<uint4*>(An + aStsB + 16) = *reinterpret_cast<uint4*>(&h[4]);
                cvt16h(&av[16], h);
                *reinterpret_cast<uint4*>(An + aStsB + 32) = *reinterpret_cast<uint4*>(&h[0]);
                *reinterpret_cast<uint4*>(An + aStsB + 48) = *reinterpret_cast<uint4*>(&h[4]);
            }
        }

        if (it + 2 < NITER) {
            asm volatile("cp.async.wait_group 1;" ::: "memory");
        } else if (it + 1 < NITER) {
            asm volatile("cp.async.wait_group 0;" ::: "memory");
        }
        __syncthreads();
    }

    // ---- epilogue: direct stores, C frag layout of m16n8
    const int g = lane >> 2;
    const int c = lane & 3;
    #pragma unroll
    for (int mt = 0; mt < 4; mt++) {
        const int row0 = by * BM + wm * 64 + mt * 16 + g;
        #pragma unroll
        for (int nt = 0; nt < 4; nt++) {
            const int col = i0 + wn * 32 + nt * 8 + c * 2;
            float* p0 = C + (size_t)row0 * E_DIM + col;
            float* p1 = C + (size_t)(row0 + 8) * E_DIM + col;
            *reinterpret_cast<float2*>(p0) = make_float2(acc[mt][nt][0], acc[mt][nt][1]);
            *reinterpret_cast<float2*>(p1) = make_float2(acc[mt][nt][2], acc[mt][nt][3]);
        }
    }
}

// ---------------- kernel 3: bias + L2 normalize (4 rows / 512-thread block) --
__global__ __launch_bounds__(512)
void bias_normalize_kernel(float* __restrict__ C, const float* __restrict__ b) {
    const int grp = threadIdx.x >> 7;          // row group 0..3 within block
    const int t   = threadIdx.x & 127;         // 0..127 within group
    const int row = blockIdx.x * 4 + grp;
    float* Cp = C + (size_t)row * E_DIM;

    float4 v  = reinterpret_cast<float4*>(Cp)[t];
    float4 bb = reinterpret_cast<const float4*>(b)[t];
    v.x += bb.x; v.y += bb.y; v.z += bb.z; v.w += bb.w;

    float ss = v.x * v.x + v.y * v.y + v.z * v.z + v.w * v.w;
    #pragma unroll
    for (int o = 16; o > 0; o >>= 1) ss += __shfl_xor_sync(0xffffffff, ss, o);

    __shared__ float warpsum[16];
    if ((t & 31) == 0) warpsum[threadIdx.x >> 5] = ss;
    __syncthreads();
    const float tot = warpsum[grp * 4 + 0] + warpsum[grp * 4 + 1] +
                      warpsum[grp * 4 + 2] + warpsum[grp * 4 + 3];
    const float scale = 1.0f / fmaxf(sqrtf(tot), 1e-12f);

    v.x *= scale; v.y *= scale; v.z *= scale; v.w *= scale;
    reinterpret_cast<float4*>(Cp)[t] = v;
}

// -----------------------------------------------------------------------------
extern "C" void kernel_launch(void* const* d_in, const int* in_sizes, int n_in,
                              void* d_out, int out_size) {
    const float* x = (const float*)d_in[0];   // (16384, 2048)
    const float* w = (const float*)d_in[1];   // (512, 1537)
    const float* b = (const float*)d_in[2];   // (512,)
    float* out = (float*)d_out;               // (16384, 512)

    cudaFuncSetAttribute(mma_gemm_kernel,
                         cudaFuncAttributeMaxDynamicSharedMemorySize, SMEM_BYTES);

    build_band_kernel<<<E_DIM, 256>>>(w);

    dim3 grid(E_DIM / BN, N_ROWS / BM);       // (4, 128)
    mma_gemm_kernel<<<grid, THREADS, SMEM_BYTES>>>(x, out);

    bias_normalize_kernel<<<N_ROWS / 4, 512>>>(out, b);
}

// round 13
// speedup vs baseline: 1.6949x; 1.6949x over previous
#include <cuda_runtime.h>
#include <cuda_fp16.h>
#include <cstdint>

// ConvEmbedding: out[n,i] = normalize_row( sum_k w[i,k]*x[n,i+k] + b[i] )
// C = X(16384x2048) @ W_band(512x2048)^T, fp16 inputs, fp32 accumulation.
// R13: R11 GEMM + bias/normalize fused into GEMM tail via per-row-block
//      completion counters (last of the 4 E-tile CTAs normalizes the block).

#define N_ROWS 16384
#define D_DIM  2048
#define E_DIM  512
#define K_DIM  1537

#define BM 128
#define BN 128
#define BK 64
#define PITCH 72                 // fp16 elems per smem row (144 B)
#define NITER 26                 // 1664 / 64, uniform for every E tile
#define THREADS 256
#define STAGES 3

#define TILE_SMEM (BM * PITCH * 2)           // 18432 B per tile
#define STAGE_SMEM (2 * TILE_SMEM)           // A, B = 36864 B
#define SMEM_BYTES (STAGES * STAGE_SMEM)     // 110592 B

#define CONV_BLOCKS 16384                    // N_ROWS*D_DIM/(256*8)
#define ROW_BLOCKS  (N_ROWS / BM)            // 128

// ---------------- scratch (device globals) ----------------------------------
__device__ __half g_Xh[(size_t)N_ROWS * D_DIM];
__device__ __half g_Wh[(size_t)E_DIM * D_DIM];
__device__ int    g_cnt[ROW_BLOCKS];

// ---------------- kernel 1: fused prep (convert X + band W + zero counters) --
__global__ __launch_bounds__(256)
void prep_kernel(const float* __restrict__ x, const float* __restrict__ w) {
    const int blk = blockIdx.x;
    if (blk < CONV_BLOCKS) {
        size_t i = ((size_t)blk * 256 + threadIdx.x) * 8;
        float4 a = *reinterpret_cast<const float4*>(x + i);
        float4 c = *reinterpret_cast<const float4*>(x + i + 4);
        __half2 h[4];
        h[0] = __float22half2_rn(make_float2(a.x, a.y));
        h[1] = __float22half2_rn(make_float2(a.z, a.w));
        h[2] = __float22half2_rn(make_float2(c.x, c.y));
        h[3] = __float22half2_rn(make_float2(c.z, c.w));
        *reinterpret_cast<uint4*>(&g_Xh[i]) = *reinterpret_cast<uint4*>(h);
        if (threadIdx.x == 0 && blk < ROW_BLOCKS) g_cnt[blk] = 0;
    } else {
        const int i = blk - CONV_BLOCKS;   // 0..511
        const float* wrow = w + (size_t)i * K_DIM;
        for (int c = threadIdx.x; c < D_DIM; c += 256) {
            const int k = c - i;
            const float val = (k >= 0 && k < K_DIM) ? wrow[k] : 0.0f;
            g_Wh[(size_t)i * D_DIM + c] = __float2half_rn(val);
        }
    }
}

// ---------------- mma helpers ------------------------------------------------
__device__ __forceinline__ void ldm_x4(uint32_t* r, uint32_t saddr) {
    asm volatile("ldmatrix.sync.aligned.m8n8.x4.shared.b16 {%0,%1,%2,%3}, [%4];"
                 : "=r"(r[0]), "=r"(r[1]), "=r"(r[2]), "=r"(r[3]) : "r"(saddr));
}
__device__ __forceinline__ void mma_f16(float* d, const uint32_t* a, const uint32_t* b) {
    asm volatile(
        "mma.sync.aligned.m16n8k16.row.col.f32.f16.f16.f32 "
        "{%0,%1,%2,%3}, {%4,%5,%6,%7}, {%8,%9}, {%0,%1,%2,%3};"
        : "+f"(d[0]), "+f"(d[1]), "+f"(d[2]), "+f"(d[3])
        : "r"(a[0]), "r"(a[1]), "r"(a[2]), "r"(a[3]), "r"(b[0]), "r"(b[1]));
}
__device__ __forceinline__ void cp_async16(uint32_t saddr, const void* gaddr) {
    asm volatile("cp.async.cg.shared.global [%0], [%1], 16;" :: "r"(saddr), "l"(gaddr));
}

// ---------------- kernel 2: fp16 GEMM + fused bias/normalize tail -------------
__global__ __launch_bounds__(THREADS, 2)
void mma_gemm_kernel(float* __restrict__ C, const float* __restrict__ b) {
    extern __shared__ __align__(128) char smem[];
    const uint32_t sb = (uint32_t)__cvta_generic_to_shared(smem);

    const int tid  = threadIdx.x;
    const int lane = tid & 31;
    const int wid  = tid >> 5;
    const int wm   = wid & 1;          // 2 warps along M
    const int wn   = wid >> 1;         // 4 warps along N
    const int bx = blockIdx.x;         // E tile (0..3)
    const int by = blockIdx.y;         // batch tile (0..127)
    const int i0 = bx * BN;
    const int kStart = i0;

    const __half* Asrc = g_Xh + (size_t)by * BM * D_DIM;
    const __half* Bsrc = g_Wh + (size_t)i0 * D_DIM;
    int lrow[4], lchk[4];
    #pragma unroll
    for (int i = 0; i < 4; i++) {
        const int v = tid + i * THREADS;   // 0..1023
        lrow[i] = v >> 3;
        lchk[i] = v & 7;
    }

    const uint32_t aoff = ((uint32_t)((wm * 64 + (lane & 15)) * PITCH + (lane >> 4) * 8)) * 2;
    const uint32_t boff = ((uint32_t)((wn * 32 + (lane >> 4) * 8 + (lane & 7)) * PITCH
                                      + ((lane >> 3) & 1) * 8)) * 2;

    float acc[4][4][4];
    #pragma unroll
    for (int mt = 0; mt < 4; mt++)
        #pragma unroll
        for (int nt = 0; nt < 4; nt++)
            #pragma unroll
            for (int q = 0; q < 4; q++) acc[mt][nt][q] = 0.0f;

    auto load_stage = [&](int s, int k0) {
        const uint32_t stg = sb + (uint32_t)s * STAGE_SMEM;
        #pragma unroll
        for (int i = 0; i < 4; i++) {
            const uint32_t so = (uint32_t)(lrow[i] * PITCH * 2 + lchk[i] * 16);
            cp_async16(stg + so,
                       Asrc + (size_t)lrow[i] * D_DIM + k0 + lchk[i] * 8);
            cp_async16(stg + TILE_SMEM + so,
                       Bsrc + (size_t)lrow[i] * D_DIM + k0 + lchk[i] * 8);
        }
        asm volatile("cp.async.commit_group;" ::: "memory");
    };

    load_stage(0, kStart);
    load_stage(1, kStart + BK);
    asm volatile("cp.async.wait_group 1;" ::: "memory");
    __syncthreads();

    for (int it = 0; it < NITER; it++) {
        if (it + 2 < NITER)
            load_stage((it + 2) % STAGES, kStart + (it + 2) * BK);

        const uint32_t stg = sb + (uint32_t)(it % STAGES) * STAGE_SMEM;
        const uint32_t sA = stg + aoff;
        const uint32_t sB = stg + TILE_SMEM + boff;

        #pragma unroll
        for (int k16 = 0; k16 < BK; k16 += 16) {
            const uint32_t ko = k16 * 2;
            uint32_t bfr[8];
            #pragma unroll
            for (int bt = 0; bt < 2; bt++)
                ldm_x4(&bfr[bt * 4], sB + (uint32_t)(bt * 16 * PITCH) * 2 + ko);

            #pragma unroll
            for (int mp = 0; mp < 2; mp++) {
                uint32_t a[8];
                #pragma unroll
                for (int m2 = 0; m2 < 2; m2++)
                    ldm_x4(&a[m2 * 4], sA + (uint32_t)((mp * 2 + m2) * 16 * PITCH) * 2 + ko);
                #pragma unroll
                for (int m2 = 0; m2 < 2; m2++)
                    #pragma unroll
                    for (int nt = 0; nt < 4; nt++)
                        mma_f16(acc[mp * 2 + m2][nt], &a[m2 * 4], &bfr[nt * 2]);
            }
        }

        if (it + 2 < NITER) {
            asm volatile("cp.async.wait_group 1;" ::: "memory");
        } else if (it + 1 < NITER) {
            asm volatile("cp.async.wait_group 0;" ::: "memory");
        }
        __syncthreads();
    }

    // ---- epilogue: add bias, store C
    const int g = lane >> 2;
    const int c = lane & 3;
    float2 bv[4];
    #pragma unroll
    for (int nt = 0; nt < 4; nt++)
        bv[nt] = *reinterpret_cast<const float2*>(b + i0 + wn * 32 + nt * 8 + c * 2);

    #pragma unroll
    for (int mt = 0; mt < 4; mt++) {
        const int row0 = by * BM + wm * 64 + mt * 16 + g;
        #pragma unroll
        for (int nt = 0; nt < 4; nt++) {
            const int col = i0 + wn * 32 + nt * 8 + c * 2;
            float* p0 = C + (size_t)row0 * E_DIM + col;
            float* p1 = C + (size_t)(row0 + 8) * E_DIM + col;
            *reinterpret_cast<float2*>(p0) =
                make_float2(acc[mt][nt][0] + bv[nt].x, acc[mt][nt][1] + bv[nt].y);
            *reinterpret_cast<float2*>(p1) =
                make_float2(acc[mt][nt][2] + bv[nt].x, acc[mt][nt][3] + bv[nt].y);
        }
    }

    // ---- completion counter: last CTA of this row block normalizes it
    __threadfence();
    __syncthreads();
    __shared__ int s_old;
    if (tid == 0) s_old = atomicAdd(&g_cnt[by], 1);
    __syncthreads();
    if (s_old != 3) return;
    __threadfence();   // order counter read before C reads

    // normalize rows by*128 .. +127 (8 warps, rows interleaved by warp)
    for (int rr = wid; rr < BM; rr += 8) {
        float* row = C + (size_t)(by * BM + rr) * E_DIM;
        float4 v0 = reinterpret_cast<float4*>(row)[lane];
        float4 v1 = reinterpret_cast<float4*>(row)[lane + 32];
        float4 v2 = reinterpret_cast<float4*>(row)[lane + 64];
        float4 v3 = reinterpret_cast<float4*>(row)[lane + 96];
        float ss = v0.x*v0.x + v0.y*v0.y + v0.z*v0.z + v0.w*v0.w
                 + v1.x*v1.x + v1.y*v1.y + v1.z*v1.z + v1.w*v1.w
                 + v2.x*v2.x + v2.y*v2.y + v2.z*v2.z + v2.w*v2.w
                 + v3.x*v3.x + v3.y*v3.y + v3.z*v3.z + v3.w*v3.w;
        #pragma unroll
        for (int o = 16; o > 0; o >>= 1) ss += __shfl_xor_sync(0xffffffff, ss, o);
        const float scale = 1.0f / fmaxf(sqrtf(ss), 1e-12f);
        v0.x*=scale; v0.y*=scale; v0.z*=scale; v0.w*=scale;
        v1.x*=scale; v1.y*=scale; v1.z*=scale; v1.w*=scale;
        v2.x*=scale; v2.y*=scale; v2.z*=scale; v2.w*=scale;
        v3.x*=scale; v3.y*=scale; v3.z*=scale; v3.w*=scale;
        reinterpret_cast<float4*>(row)[lane]      = v0;
        reinterpret_cast<float4*>(row)[lane + 32] = v1;
        reinterpret_cast<float4*>(row)[lane + 64] = v2;
        reinterpret_cast<float4*>(row)[lane + 96] = v3;
    }
}

// -----------------------------------------------------------------------------
extern "C" void kernel_launch(void* const* d_in, const int* in_sizes, int n_in,
                              void* d_out, int out_size) {
    const float* x = (const float*)d_in[0];   // (16384, 2048)
    const float* w = (const float*)d_in[1];   // (512, 1537)
    const float* b = (const float*)d_in[2];   // (512,)
    float* out = (float*)d_out;               // (16384, 512)

    cudaFuncSetAttribute(mma_gemm_kernel,
                         cudaFuncAttributeMaxDynamicSharedMemorySize, SMEM_BYTES);

    prep_kernel<<<CONV_BLOCKS + E_DIM, 256>>>(x, w);

    dim3 grid(E_DIM / BN, N_ROWS / BM);       // (4, 128)
    mma_gemm_kernel<<<grid, THREADS, SMEM_BYTES>>>(out, b);
}

// round 14
// speedup vs baseline: 1.8675x; 1.1019x over previous
#include <cuda_runtime.h>
#include <cuda_fp16.h>
#include <cstdint>

// ConvEmbedding: out[n,i] = normalize_row( sum_k w[i,k]*x[n,i+k] + b[i] )
// C = X(16384x2048) @ W_band(512x2048)^T, fp16 inputs, fp32 accumulation.
// R14: R11 GEMM (HMMA floor) + higher-MLP prep + warp-per-row normalize.

#define N_ROWS 16384
#define D_DIM  2048
#define E_DIM  512
#define K_DIM  1537

#define BM 128
#define BN 128
#define BK 64
#define PITCH 72                 // fp16 elems per smem row (144 B)
#define NITER 26                 // 1664 / 64, uniform for every E tile
#define THREADS 256
#define STAGES 3

#define TILE_SMEM (BM * PITCH * 2)           // 18432 B per tile
#define STAGE_SMEM (2 * TILE_SMEM)           // A, B = 36864 B
#define SMEM_BYTES (STAGES * STAGE_SMEM)     // 110592 B

#define CONV_BLOCKS 8192                     // N_ROWS*D_DIM/(256*16)

// ---------------- scratch (device globals) ----------------------------------
__device__ __half g_Xh[(size_t)N_ROWS * D_DIM];
__device__ __half g_Wh[(size_t)E_DIM * D_DIM];

// ---------------- kernel 1: fused prep (convert X + build banded W) ----------
// X-convert: 16 fp32 per thread as two independent 32B load streams (MLP=4).
__global__ __launch_bounds__(256)
void prep_kernel(const float* __restrict__ x, const float* __restrict__ w) {
    const int blk = blockIdx.x;
    if (blk < CONV_BLOCKS) {
        const size_t base = ((size_t)blk * 256 + threadIdx.x) * 8;
        const size_t half = (size_t)CONV_BLOCKS * 256 * 8;   // second stream offset
        float4 a0 = *reinterpret_cast<const float4*>(x + base);
        float4 a1 = *reinterpret_cast<const float4*>(x + base + 4);
        float4 b0 = *reinterpret_cast<const float4*>(x + half + base);
        float4 b1 = *reinterpret_cast<const float4*>(x + half + base + 4);
        __half2 h[4];
        h[0] = __float22half2_rn(make_float2(a0.x, a0.y));
        h[1] = __float22half2_rn(make_float2(a0.z, a0.w));
        h[2] = __float22half2_rn(make_float2(a1.x, a1.y));
        h[3] = __float22half2_rn(make_float2(a1.z, a1.w));
        *reinterpret_cast<uint4*>(&g_Xh[base]) = *reinterpret_cast<uint4*>(h);
        h[0] = __float22half2_rn(make_float2(b0.x, b0.y));
        h[1] = __float22half2_rn(make_float2(b0.z, b0.w));
        h[2] = __float22half2_rn(make_float2(b1.x, b1.y));
        h[3] = __float22half2_rn(make_float2(b1.z, b1.w));
        *reinterpret_cast<uint4*>(&g_Xh[half + base]) = *reinterpret_cast<uint4*>(h);
    } else {
        const int i = blk - CONV_BLOCKS;   // 0..511
        const float* wrow = w + (size_t)i * K_DIM;
        for (int c = threadIdx.x; c < D_DIM; c += 256) {
            const int k = c - i;
            const float val = (k >= 0 && k < K_DIM) ? wrow[k] : 0.0f;
            g_Wh[(size_t)i * D_DIM + c] = __float2half_rn(val);
        }
    }
}

// ---------------- mma helpers ------------------------------------------------
__device__ __forceinline__ void ldm_x4(uint32_t* r, uint32_t saddr) {
    asm volatile("ldmatrix.sync.aligned.m8n8.x4.shared.b16 {%0,%1,%2,%3}, [%4];"
                 : "=r"(r[0]), "=r"(r[1]), "=r"(r[2]), "=r"(r[3]) : "r"(saddr));
}
__device__ __forceinline__ void mma_f16(float* d, const uint32_t* a, const uint32_t* b) {
    asm volatile(
        "mma.sync.aligned.m16n8k16.row.col.f32.f16.f16.f32 "
        "{%0,%1,%2,%3}, {%4,%5,%6,%7}, {%8,%9}, {%0,%1,%2,%3};"
        : "+f"(d[0]), "+f"(d[1]), "+f"(d[2]), "+f"(d[3])
        : "r"(a[0]), "r"(a[1]), "r"(a[2]), "r"(a[3]), "r"(b[0]), "r"(b[1]));
}
__device__ __forceinline__ void cp_async16(uint32_t saddr, const void* gaddr) {
    asm volatile("cp.async.cg.shared.global [%0], [%1], 16;" :: "r"(saddr), "l"(gaddr));
}

// ---------------- kernel 2: fp16 GEMM (R11, unchanged) ------------------------
__global__ __launch_bounds__(THREADS, 2)
void mma_gemm_kernel(float* __restrict__ C) {
    extern __shared__ __align__(128) char smem[];
    const uint32_t sb = (uint32_t)__cvta_generic_to_shared(smem);

    const int tid  = threadIdx.x;
    const int lane = tid & 31;
    const int wid  = tid >> 5;
    const int wm   = wid & 1;          // 2 warps along M
    const int wn   = wid >> 1;         // 4 warps along N
    const int bx = blockIdx.x;         // E tile (0..3)
    const int by = blockIdx.y;         // batch tile (0..127)
    const int i0 = bx * BN;
    const int kStart = i0;

    const __half* Asrc = g_Xh + (size_t)by * BM * D_DIM;
    const __half* Bsrc = g_Wh + (size_t)i0 * D_DIM;
    int lrow[4], lchk[4];
    #pragma unroll
    for (int i = 0; i < 4; i++) {
        const int v = tid + i * THREADS;   // 0..1023
        lrow[i] = v >> 3;
        lchk[i] = v & 7;
    }

    const uint32_t aoff = ((uint32_t)((wm * 64 + (lane & 15)) * PITCH + (lane >> 4) * 8)) * 2;
    const uint32_t boff = ((uint32_t)((wn * 32 + (lane >> 4) * 8 + (lane & 7)) * PITCH
                                      + ((lane >> 3) & 1) * 8)) * 2;

    float acc[4][4][4];
    #pragma unroll
    for (int mt = 0; mt < 4; mt++)
        #pragma unroll
        for (int nt = 0; nt < 4; nt++)
            #pragma unroll
            for (int q = 0; q < 4; q++) acc[mt][nt][q] = 0.0f;

    auto load_stage = [&](int s, int k0) {
        const uint32_t stg = sb + (uint32_t)s * STAGE_SMEM;
        #pragma unroll
        for (int i = 0; i < 4; i++) {
            const uint32_t so = (uint32_t)(lrow[i] * PITCH * 2 + lchk[i] * 16);
            cp_async16(stg + so,
                       Asrc + (size_t)lrow[i] * D_DIM + k0 + lchk[i] * 8);
            cp_async16(stg + TILE_SMEM + so,
                       Bsrc + (size_t)lrow[i] * D_DIM + k0 + lchk[i] * 8);
        }
        asm volatile("cp.async.commit_group;" ::: "memory");
    };

    load_stage(0, kStart);
    load_stage(1, kStart + BK);
    asm volatile("cp.async.wait_group 1;" ::: "memory");
    __syncthreads();

    for (int it = 0; it < NITER; it++) {
        if (it + 2 < NITER)
            load_stage((it + 2) % STAGES, kStart + (it + 2) * BK);

        const uint32_t stg = sb + (uint32_t)(it % STAGES) * STAGE_SMEM;
        const uint32_t sA = stg + aoff;
        const uint32_t sB = stg + TILE_SMEM + boff;

        #pragma unroll
        for (int k16 = 0; k16 < BK; k16 += 16) {
            const uint32_t ko = k16 * 2;
            uint32_t bfr[8];
            #pragma unroll
            for (int bt = 0; bt < 2; bt++)
                ldm_x4(&bfr[bt * 4], sB + (uint32_t)(bt * 16 * PITCH) * 2 + ko);

            #pragma unroll
            for (int mp = 0; mp < 2; mp++) {
                uint32_t a[8];
                #pragma unroll
                for (int m2 = 0; m2 < 2; m2++)
                    ldm_x4(&a[m2 * 4], sA + (uint32_t)((mp * 2 + m2) * 16 * PITCH) * 2 + ko);
                #pragma unroll
                for (int m2 = 0; m2 < 2; m2++)
                    #pragma unroll
                    for (int nt = 0; nt < 4; nt++)
                        mma_f16(acc[mp * 2 + m2][nt], &a[m2 * 4], &bfr[nt * 2]);
            }
        }

        if (it + 2 < NITER) {
            asm volatile("cp.async.wait_group 1;" ::: "memory");
        } else if (it + 1 < NITER) {
            asm volatile("cp.async.wait_group 0;" ::: "memory");
        }
        __syncthreads();
    }

    const int g = lane >> 2;
    const int c = lane & 3;
    #pragma unroll
    for (int mt = 0; mt < 4; mt++) {
        const int row0 = by * BM + wm * 64 + mt * 16 + g;
        #pragma unroll
        for (int nt = 0; nt < 4; nt++) {
            const int col = i0 + wn * 32 + nt * 8 + c * 2;
            float* p0 = C + (size_t)row0 * E_DIM + col;
            float* p1 = C + (size_t)(row0 + 8) * E_DIM + col;
            *reinterpret_cast<float2*>(p0) = make_float2(acc[mt][nt][0], acc[mt][nt][1]);
            *reinterpret_cast<float2*>(p1) = make_float2(acc[mt][nt][2], acc[mt][nt][3]);
        }
    }
}

// ---------------- kernel 3: bias + L2 normalize (warp per row, no barriers) --
__global__ __launch_bounds__(256)
void bias_normalize_kernel(float* __restrict__ C, const float* __restrict__ b) {
    const int lane = threadIdx.x & 31;
    const int wrp  = threadIdx.x >> 5;           // 0..7
    const int row  = blockIdx.x * 8 + wrp;
    float* Cp = C + (size_t)row * E_DIM;

    // 512 floats per row / 32 lanes = 16 per lane = 4 float4
    float4 v[4], bb[4];
    #pragma unroll
    for (int q = 0; q < 4; q++) {
        v[q]  = reinterpret_cast<float4*>(Cp)[lane + q * 32];
        bb[q] = reinterpret_cast<const float4*>(b)[lane + q * 32];
        v[q].x += bb[q].x; v[q].y += bb[q].y; v[q].z += bb[q].z; v[q].w += bb[q].w;
    }

    float ss = 0.0f;
    #pragma unroll
    for (int q = 0; q < 4; q++)
        ss += v[q].x * v[q].x + v[q].y * v[q].y + v[q].z * v[q].z + v[q].w * v[q].w;
    #pragma unroll
    for (int o = 16; o > 0; o >>= 1) ss += __shfl_xor_sync(0xffffffff, ss, o);

    const float scale = 1.0f / fmaxf(sqrtf(ss), 1e-12f);
    #pragma unroll
    for (int q = 0; q < 4; q++) {
        v[q].x *= scale; v[q].y *= scale; v[q].z *= scale; v[q].w *= scale;
        reinterpret_cast<float4*>(Cp)[lane + q * 32] = v[q];
    }
}

// -----------------------------------------------------------------------------
extern "C" void kernel_launch(void* const* d_in, const int* in_sizes, int n_in,
                              void* d_out, int out_size) {
    const float* x = (const float*)d_in[0];   // (16384, 2048)
    const float* w = (const float*)d_in[1];   // (512, 1537)
    const float* b = (const float*)d_in[2];   // (512,)
    float* out = (float*)d_out;               // (16384, 512)

    cudaFuncSetAttribute(mma_gemm_kernel,
                         cudaFuncAttributeMaxDynamicSharedMemorySize, SMEM_BYTES);

    prep_kernel<<<CONV_BLOCKS + E_DIM, 256>>>(x, w);

    dim3 grid(E_DIM / BN, N_ROWS / BM);       // (4, 128)
    mma_gemm_kernel<<<grid, THREADS, SMEM_BYTES>>>(out);

    bias_normalize_kernel<<<N_ROWS / 8, 256>>>(out, b);
}